// round 12
// baseline (speedup 1.0000x reference)
#include <cuda_runtime.h>
#include <cuda_fp16.h>
#include <cstdint>

// ============================================================================
// MHMLP: out[b,h] = lrelu( sum_n lrelu( x[b,:]·W1[h,:,n] + b1[h,n] ) * W2[h,n] + b2[h] )
// B=2048, H=64, D=512(K), HID=2048(N). fp32 in/out, fp16 HMMA (rt4 full-rate).
// R12 = R5 mainloop (champion) with the fp16 PREPASS FUSED INTO THE KERNEL:
// W fill reads fp32 W1 directly (LDG.128 x2 -> cvt -> STS.128), software-
// pipelined through the ks loop (one float4-pair staged). X tile converted
// inline at CTA init. No prepass kernels, no device globals, ONE launch.
// ============================================================================
#define BB   2048
#define HH   64
#define DD   512
#define HID  2048

__device__ __forceinline__ uint32_t smem_to_u32(const void* p) {
    uint32_t a;
    asm("{ .reg .u64 t; cvta.to.shared.u64 t, %1; cvt.u32.u64 %0, t; }" : "=r"(a) : "l"(p));
    return a;
}

#define STS128(addr, v) \
    asm volatile("st.shared.v4.b32 [%0], {%1,%2,%3,%4};" \
        :: "r"(addr), "r"((v).x), "r"((v).y), "r"((v).z), "r"((v).w) : "memory")

#define LDSM_X4(r0, r1, r2, r3, addr) \
    asm volatile("ldmatrix.sync.aligned.m8n8.x4.shared.b16 {%0,%1,%2,%3}, [%4];" \
        : "=r"(r0), "=r"(r1), "=r"(r2), "=r"(r3) : "r"(addr))
#define LDSM_X4_T(r0, r1, r2, r3, addr) \
    asm volatile("ldmatrix.sync.aligned.m8n8.x4.trans.shared.b16 {%0,%1,%2,%3}, [%4];" \
        : "=r"(r0), "=r"(r1), "=r"(r2), "=r"(r3) : "r"(addr))

__device__ __forceinline__ void mma16816(float* c, const uint32_t* a, const uint32_t* b) {
    asm volatile(
        "mma.sync.aligned.m16n8k16.row.col.f32.f16.f16.f32 "
        "{%0,%1,%2,%3}, {%4,%5,%6,%7}, {%8,%9}, {%0,%1,%2,%3};"
        : "+f"(c[0]), "+f"(c[1]), "+f"(c[2]), "+f"(c[3])
        : "r"(a[0]), "r"(a[1]), "r"(a[2]), "r"(a[3]), "r"(b[0]), "r"(b[1]));
}

__device__ __forceinline__ float lrelu(float v) {
    return fmaxf(v, 0.f) + 0.01f * fminf(v, 0.f);
}

__device__ __forceinline__ uint4 cvt8(float4 a, float4 b) {
    __half2 h0 = __floats2half2_rn(a.x, a.y), h1 = __floats2half2_rn(a.z, a.w);
    __half2 h2 = __floats2half2_rn(b.x, b.y), h3 = __floats2half2_rn(b.z, b.w);
    uint4 o;
    o.x = *reinterpret_cast<uint32_t*>(&h0);
    o.y = *reinterpret_cast<uint32_t*>(&h1);
    o.z = *reinterpret_cast<uint32_t*>(&h2);
    o.w = *reinterpret_cast<uint32_t*>(&h3);
    return o;
}

// ============================================================================
// Main (only) kernel
// Grid: 1024 = 64 heads x 16 m-tiles. 512 threads = 16 warps.
// Warps 0-7 = half 0 (n-chunks 0-7), warps 8-15 = half 1 (n-chunks 8-15).
// Each half: 4m x 2n warps, warp tile 32m x 64n, W double buffer (16KB fp16
// chunks) filled by inline fp32->fp16 conversion, own named barrier.
//
// SMEM:
//   [0..131072)        X: [kb][128m][64k halves], 128B rows, swizzled
//   [131072..196608)   W: 2 halves x 2 bufs x (64k x 128n), 256B rows, swizzled
//   [196608..212992)   bw: float2[2048] = (b1, W2)
//   [212992..215040)   part: float[128][4]
// ============================================================================
#define SM_X    0
#define SM_W    131072
#define SM_BW   196608
#define SM_PART 212992
#define SMEM_TOTAL 215040
#define NTHREADS 512

__global__ void __launch_bounds__(NTHREADS, 1) mhmlp_main(
    const float* __restrict__ xg,  const float* __restrict__ W1g,
    const float* __restrict__ b1g, const float* __restrict__ w2g,
    const float* __restrict__ b2g, float* __restrict__ out)
{
    extern __shared__ char smem[];
    uint32_t sb = smem_to_u32(smem);
    int tid  = threadIdx.x;
    int lane = tid & 31;
    int wid  = tid >> 5;
    int half = wid >> 3;        // 0 or 1
    int hw   = wid & 7;
    int wm   = hw >> 1;         // 0..3 (32-row band)
    int wn   = hw & 1;          // 0..1 (64-col half of the 128n chunk)
    int ht   = tid & 255;       // thread index within half
    int h  = blockIdx.x >> 4;
    int m0 = (blockIdx.x & 15) * 128;

    const float* Wh = W1g + (size_t)h * DD * HID;   // [d][n] fp32 for this head

    // ---- X tile: inline fp32->fp16 convert into swizzled smem ----
#pragma unroll 4
    for (int i = 0; i < 16; ++i) {
        int idx = i * NTHREADS + tid;                // 8192 16B-fp16 units
        int m = idx >> 6, j = idx & 63;              // j: 8-fp32 group in k
        const float4* ps = reinterpret_cast<const float4*>(
            xg + (size_t)(m0 + m) * DD + j * 8);
        float4 a = ps[0], b = ps[1];
        int kb = j >> 3, jj = j & 7;
        uint32_t dst = sb + SM_X + kb * 16384 + m * 128 + ((jj * 16) ^ ((m & 7) << 4));
        uint4 o = cvt8(a, b);
        STS128(dst, o);
    }

    // ---- W chunk 0 for this half: inline convert ----
    {
        const float* fW = Wh + (size_t)(half * 8) * 128;   // kb=0, nc=half*8
        uint32_t fbase = sb + SM_W + half * 32768;          // buf 0
#pragma unroll
        for (int p = 0; p < 4; ++p) {
            int idx = p * 256 + ht;                  // 1024 16B-fp16 units
            int kr = idx >> 4, j = idx & 15;
            const float4* ps = reinterpret_cast<const float4*>(
                fW + (size_t)kr * HID + j * 8);
            float4 a = ps[0], b = ps[1];
            uint32_t dst = fbase + kr * 256 + ((j * 16) ^ ((kr & 7) << 4));
            uint4 o = cvt8(a, b);
            STS128(dst, o);
        }
    }

    // ---- bias/W2 table into smem ----
    float2* bw = reinterpret_cast<float2*>(smem + SM_BW);
#pragma unroll
    for (int i = 0; i < 4; ++i) {
        int n = i * NTHREADS + tid;
        bw[n] = make_float2(b1g[h * HID + n], w2g[h * HID + n]);
    }
    __syncthreads();            // drains all STS; X + W0 + bw visible

    float acc[2][8][4];
#pragma unroll
    for (int mi = 0; mi < 2; ++mi)
#pragma unroll
        for (int ni = 0; ni < 8; ++ni)
#pragma unroll
            for (int r = 0; r < 4; ++r) acc[mi][ni][r] = 0.f;
    float rowacc[4] = {0.f, 0.f, 0.f, 0.f};

    int la = lane & 15;
    int lb = lane >> 4;
    int lmask = (lane & 7) << 4;
    int barid = 1 + half;

    uint32_t fa[2][4];
    uint32_t fb[4][4];

    // fill-unit geometry for this thread (pair p has idx = p*256 + ht)
    int fkr = ht >> 4;          // row for pair 0; pair p adds p*16 rows
    int fj  = ht & 15;          // 16B chunk in row (constant across pairs)
    uint32_t fswz = (uint32_t)((fj * 16) ^ ((fkr & 7) << 4));  // kr&7 invariant (+16 rows)

    for (int t = 0; t < 64; ++t) {
        // top barrier: W(t) STS (done during t-1) drained + visible; WAR safe
        asm volatile("bar.sync %0, %1;" :: "r"(barid), "r"(256) : "memory");

        int nc = half * 8 + (t >> 3);
        int kb = t & 7;
        uint32_t abase = sb + SM_X + kb * 16384;
        uint32_t bbase = sb + SM_W + half * 32768 + (t & 1) * 16384;

        // fill setup for chunk c = t+1 into buffer (t+1)&1
        bool fill = (t + 1 < 64);
        int c = t + 1;
        const float* fW = Wh + ((size_t)((c & 7) * 64) * HID
                                + (size_t)(half * 8 + (c >> 3)) * 128)
                             + (size_t)fkr * HID + fj * 8;
        uint32_t fdst = sb + SM_W + half * 32768 + (c & 1) * 16384
                        + fkr * 256 + fswz;
        float4 s0, s1;
        if (fill) {             // load pair 0
            const float4* ps = reinterpret_cast<const float4*>(fW);
            s0 = ps[0]; s1 = ps[1];
        }

#pragma unroll
        for (int ks = 0; ks < 4; ++ks) {
            if (fill && ks > 0) {
                // store pair ks-1, then load pair ks (+16 rows per pair)
                uint4 o = cvt8(s0, s1);
                STS128(fdst + (ks - 1) * 16 * 256, o);
                const float4* ps = reinterpret_cast<const float4*>(
                    fW + (size_t)ks * 16 * HID);
                s0 = ps[0]; s1 = ps[1];
            }
#pragma unroll
            for (int mi = 0; mi < 2; ++mi) {
                int m = wm * 32 + mi * 16 + la;
                uint32_t ad = abase + m * 128 + ((ks * 32 + lb * 16) ^ lmask);
                LDSM_X4(fa[mi][0], fa[mi][1], fa[mi][2], fa[mi][3], ad);
            }
#pragma unroll
            for (int nb = 0; nb < 4; ++nb) {
                int kr = ks * 16 + la;
                uint32_t bd = bbase + kr * 256 +
                              (((wn * 64 + nb * 16 + lb * 8) * 2) ^ lmask);
                LDSM_X4_T(fb[nb][0], fb[nb][1], fb[nb][2], fb[nb][3], bd);
            }
#pragma unroll
            for (int mi = 0; mi < 2; ++mi)
#pragma unroll
                for (int ni = 0; ni < 8; ++ni)
                    mma16816(acc[mi][ni], fa[mi], &fb[ni >> 1][(ni & 1) * 2]);
        }
        if (fill) {             // store pair 3
            uint4 o = cvt8(s0, s1);
            STS128(fdst + 3 * 16 * 256, o);
        }

        if (kb == 7) {
            // fold 128-col n-chunk: bias + leaky + dot(W2)
            int ncb = nc * 128 + wn * 64 + (lane & 3) * 2;
#pragma unroll
            for (int ni = 0; ni < 8; ++ni) {
                int n = ncb + ni * 8;
                float2 p0 = bw[n];
                float2 p1 = bw[n + 1];
#pragma unroll
                for (int mi = 0; mi < 2; ++mi) {
                    rowacc[mi * 2 + 0] = fmaf(lrelu(acc[mi][ni][0] + p0.x), p0.y, rowacc[mi * 2 + 0]);
                    rowacc[mi * 2 + 0] = fmaf(lrelu(acc[mi][ni][1] + p1.x), p1.y, rowacc[mi * 2 + 0]);
                    rowacc[mi * 2 + 1] = fmaf(lrelu(acc[mi][ni][2] + p0.x), p0.y, rowacc[mi * 2 + 1]);
                    rowacc[mi * 2 + 1] = fmaf(lrelu(acc[mi][ni][3] + p1.x), p1.y, rowacc[mi * 2 + 1]);
                    acc[mi][ni][0] = 0.f; acc[mi][ni][1] = 0.f;
                    acc[mi][ni][2] = 0.f; acc[mi][ni][3] = 0.f;
                }
            }
        }
    }

    // ---- reduce rowacc across the 4 lanes sharing each row ----
#pragma unroll
    for (int i = 0; i < 4; ++i) {
        rowacc[i] += __shfl_xor_sync(0xffffffffu, rowacc[i], 1);
        rowacc[i] += __shfl_xor_sync(0xffffffffu, rowacc[i], 2);
    }
    float* part = reinterpret_cast<float*>(smem + SM_PART);
    if ((lane & 3) == 0) {
        int rq = lane >> 2;
        int rbase = wm * 32;
        int col = half * 2 + wn;
        part[(rbase +  0 + rq) * 4 + col] = rowacc[0];
        part[(rbase +  8 + rq) * 4 + col] = rowacc[1];
        part[(rbase + 16 + rq) * 4 + col] = rowacc[2];
        part[(rbase + 24 + rq) * 4 + col] = rowacc[3];
    }
    __syncthreads();
    if (tid < 128) {
        float s = part[tid * 4] + part[tid * 4 + 1] + part[tid * 4 + 2] +
                  part[tid * 4 + 3] + b2g[h];
        s = lrelu(s);
        out[(size_t)(m0 + tid) * HH + h] = s;
    }
}

// ============================================================================
// Launch: ONE kernel, no prepass, no streams, no device scratch.
// ============================================================================
extern "C" void kernel_launch(void* const* d_in, const int* in_sizes, int n_in,
                              void* d_out, int out_size) {
    const float* x  = (const float*)d_in[0];
    const float* W1 = (const float*)d_in[1];
    const float* b1 = (const float*)d_in[2];
    const float* W2 = (const float*)d_in[3];
    const float* b2 = (const float*)d_in[4];
    float* out = (float*)d_out;

    cudaFuncSetAttribute(mhmlp_main, cudaFuncAttributeMaxDynamicSharedMemorySize, SMEM_TOTAL);
    mhmlp_main<<<1024, NTHREADS, SMEM_TOTAL>>>(x, W1, b1, W2, b2, out);
}

// round 13
// speedup vs baseline: 1.4023x; 1.4023x over previous
#include <cuda_runtime.h>
#include <cuda_fp16.h>
#include <cstdint>

// ============================================================================
// MHMLP: out[b,h] = lrelu( sum_n lrelu( x[b,:]·W1[h,:,n] + b1[h,n] ) * W2[h,n] + b2[h] )
// B=2048, H=64, D=512(K), HID=2048(N). fp32 in/out, fp16 HMMA (rt4 full-rate).
// R13 = R5 mainloop (champion) made PERSISTENT: grid 148, each CTA runs ~7
// tiles; next tile's X blocks 0-6 + W chunk0 prefetched at t=63 (full bar),
// X[7] at t=1 (full bars at t=0,2 order it). W pipeline never drains across
// tiles; per-wave synchronized startup bursts (~3.4us x 7) are eliminated.
// Prepass (fp32->fp16, DRAM-roofline ~51us) unchanged.
// ============================================================================
#define BB   2048
#define HH   64
#define DD   512
#define HID  2048
#define NSM  148
#define NTILES 1024

__device__ __half  g_W16[(size_t)HH * DD * HID];    // [h][d][n] fp16
__device__ __half  g_X16[(size_t)BB * DD];          // [b][d]   fp16

__device__ __forceinline__ uint32_t smem_to_u32(const void* p) {
    uint32_t a;
    asm("{ .reg .u64 t; cvta.to.shared.u64 t, %1; cvt.u32.u64 %0, t; }" : "=r"(a) : "l"(p));
    return a;
}
__device__ __forceinline__ void cp_async_16(uint32_t dst, const void* src) {
    asm volatile("cp.async.cg.shared.global [%0], [%1], 16;" :: "r"(dst), "l"(src));
}
#define CP_COMMIT()   asm volatile("cp.async.commit_group;" ::: "memory")
#define CP_WAIT0()    asm volatile("cp.async.wait_group 0;" ::: "memory")

#define LDSM_X4(r0, r1, r2, r3, addr) \
    asm volatile("ldmatrix.sync.aligned.m8n8.x4.shared.b16 {%0,%1,%2,%3}, [%4];" \
        : "=r"(r0), "=r"(r1), "=r"(r2), "=r"(r3) : "r"(addr))
#define LDSM_X4_T(r0, r1, r2, r3, addr) \
    asm volatile("ldmatrix.sync.aligned.m8n8.x4.trans.shared.b16 {%0,%1,%2,%3}, [%4];" \
        : "=r"(r0), "=r"(r1), "=r"(r2), "=r"(r3) : "r"(addr))

__device__ __forceinline__ void mma16816(float* c, const uint32_t* a, const uint32_t* b) {
    asm volatile(
        "mma.sync.aligned.m16n8k16.row.col.f32.f16.f16.f32 "
        "{%0,%1,%2,%3}, {%4,%5,%6,%7}, {%8,%9}, {%0,%1,%2,%3};"
        : "+f"(c[0]), "+f"(c[1]), "+f"(c[2]), "+f"(c[3])
        : "r"(a[0]), "r"(a[1]), "r"(a[2]), "r"(a[3]), "r"(b[0]), "r"(b[1]));
}

__device__ __forceinline__ float lrelu(float v) {
    return fmaxf(v, 0.f) + 0.01f * fminf(v, 0.f);
}

// ============================================================================
// Merged pre-pass: x fp32->fp16 (blocks [0,512)), W1 fp32->fp16 ([512,33280))
// ============================================================================
__global__ void convert_all_kernel(const float* __restrict__ x,
                                   const float* __restrict__ W1) {
    const float* src;
    __half* dst;
    size_t g;
    if (blockIdx.x < 512) {
        g = (size_t)blockIdx.x * 256 + threadIdx.x;
        src = x;  dst = g_X16;
    } else {
        g = (size_t)(blockIdx.x - 512) * 256 + threadIdx.x;
        src = W1; dst = g_W16;
    }
    const float4* p = reinterpret_cast<const float4*>(src) + g * 2;
    float4 a = p[0], b = p[1];
    __half2 h0 = __floats2half2_rn(a.x, a.y), h1 = __floats2half2_rn(a.z, a.w);
    __half2 h2 = __floats2half2_rn(b.x, b.y), h3 = __floats2half2_rn(b.z, b.w);
    uint4 o;
    o.x = *reinterpret_cast<uint32_t*>(&h0);
    o.y = *reinterpret_cast<uint32_t*>(&h1);
    o.z = *reinterpret_cast<uint32_t*>(&h2);
    o.w = *reinterpret_cast<uint32_t*>(&h3);
    *reinterpret_cast<uint4*>(dst + g * 8) = o;
}

// ============================================================================
// Main persistent kernel
// Grid: 148 CTAs, each loops tiles (tile = bid, bid+148, ...; 1024 tiles =
// 64 heads x 16 m-tiles). 512 threads = 16 warps, two independent n-halves
// (4m x 2n warps each, warp tile 32m x 64n), W double buffer per half.
// Full __syncthreads at t=0,2,63 (cross-half ordering for X prefetch);
// half-local named barriers elsewhere (the R5 decoupling that won).
//
// SMEM:
//   [0..131072)        X: [kb][128m][64k halves], 128B rows, swizzled
//   [131072..196608)   W: 2 halves x 2 bufs x (64k x 128n), 256B rows, swizzled
//   [196608..212992)   bw: float2[2048] = (b1, W2) of the current tile's head
//   [212992..215040)   part: float[128][4]
// ============================================================================
#define SM_X    0
#define SM_W    131072
#define SM_BW   196608
#define SM_PART 212992
#define SMEM_TOTAL 215040
#define NTHREADS 512

// fill W chunk c (c in [0,64): nc_local=c>>3, kb=c&7) into buffer (c&1)
__device__ __forceinline__ void fill_w_chunk(const __half* __restrict__ Wh,
                                             uint32_t sb, int half, int c, int ht) {
    int nc = half * 8 + (c >> 3);
    int kb = c & 7;
    uint32_t base = sb + SM_W + half * 32768 + (c & 1) * 16384;
    const __half* src = Wh + (size_t)(kb * 64) * HID + nc * 128;
#pragma unroll
    for (int i = 0; i < 4; ++i) {
        int idx = i * 256 + ht;
        int kr = idx >> 4, j = idx & 15;
        uint32_t dst = base + kr * 256 + ((j * 16) ^ ((kr & 7) << 4));
        cp_async_16(dst, src + (size_t)kr * HID + j * 8);
    }
}

// fill X block kb (16KB) for m-tile m0; all 512 threads, 2 chunks each
__device__ __forceinline__ void fill_x_block(uint32_t sb, int m0, int kb, int tid) {
#pragma unroll
    for (int q = 0; q < 2; ++q) {
        int idx = q * NTHREADS + tid;            // 1024 chunks of 16B
        int m = idx >> 3, jj = idx & 7;
        uint32_t dst = sb + SM_X + kb * 16384 + m * 128 + ((jj * 16) ^ ((m & 7) << 4));
        cp_async_16(dst, g_X16 + (size_t)(m0 + m) * DD + kb * 64 + jj * 8);
    }
}

__global__ void __launch_bounds__(NTHREADS, 1) mhmlp_main(
    const float* __restrict__ b1g, const float* __restrict__ w2g,
    const float* __restrict__ b2g, float* __restrict__ out)
{
    extern __shared__ char smem[];
    uint32_t sb = smem_to_u32(smem);
    int tid  = threadIdx.x;
    int lane = tid & 31;
    int wid  = tid >> 5;
    int half = wid >> 3;        // 0 or 1
    int hw   = wid & 7;
    int wm   = hw >> 1;         // 0..3 (32-row band)
    int wn   = hw & 1;          // 0..1 (64-col half of the 128n chunk)
    int ht   = tid & 255;       // thread index within half
    int bid  = blockIdx.x;

    float2* bw = reinterpret_cast<float2*>(smem + SM_BW);
    float* part = reinterpret_cast<float*>(smem + SM_PART);

    int la = lane & 15;
    int lb = lane >> 4;
    int lmask = (lane & 7) << 4;
    int barid = 1 + half;

    float acc[2][8][4];
#pragma unroll
    for (int mi = 0; mi < 2; ++mi)
#pragma unroll
        for (int ni = 0; ni < 8; ++ni)
#pragma unroll
            for (int r = 0; r < 4; ++r) acc[mi][ni][r] = 0.f;
    float rowacc[4] = {0.f, 0.f, 0.f, 0.f};

    uint32_t fa[2][4];
    uint32_t fb[4][4];

    for (int tile = bid; tile < NTILES; tile += NSM) {
        int h  = tile >> 4;
        int m0 = (tile & 15) * 128;
        bool first = (tile == bid);
        const __half* Wh = g_W16 + (size_t)h * DD * HID;

        if (first) {
            // startup: all X blocks + W chunk0 + bw (drained at t=0 full sync)
#pragma unroll
            for (int kb = 0; kb < 8; ++kb) fill_x_block(sb, m0, kb, tid);
            fill_w_chunk(Wh, sb, half, 0, ht);
            CP_COMMIT();
#pragma unroll
            for (int i = 0; i < 4; ++i) {
                int n = half * 1024 + i * 256 + ht;
                bw[n] = make_float2(b1g[h * HID + n], w2g[h * HID + n]);
            }
        }
        // non-first tiles: X[0..6] + W chunk0 prefetched at prev t=63;
        // bw reloaded in prev epilogue; X[7] filled below at t=1.

        for (int t = 0; t < 64; ++t) {
            CP_WAIT0();         // drain fills committed last iteration
            if (t == 0 || t == 2 || t == 63)
                __syncthreads();                       // cross-half ordering
            else
                asm volatile("bar.sync %0, %1;" :: "r"(barid), "r"(256) : "memory");

            // fills for the future
            if (t < 63) {
                fill_w_chunk(Wh, sb, half, t + 1, ht);
                if (t == 1 && !first) fill_x_block(sb, m0, 7, tid);
            } else if (tile + NSM < NTILES) {
                int tn = tile + NSM;
                const __half* WhN = g_W16 + (size_t)(tn >> 4) * DD * HID;
                fill_w_chunk(WhN, sb, half, 0, ht);
                int m0n = (tn & 15) * 128;
#pragma unroll
                for (int kb = 0; kb < 7; ++kb) fill_x_block(sb, m0n, kb, tid);
            }
            CP_COMMIT();

            int nc = half * 8 + (t >> 3);
            int kb = t & 7;
            uint32_t abase = sb + SM_X + kb * 16384;
            uint32_t bbase = sb + SM_W + half * 32768 + (t & 1) * 16384;

#pragma unroll
            for (int ks = 0; ks < 4; ++ks) {
#pragma unroll
                for (int mi = 0; mi < 2; ++mi) {
                    int m = wm * 32 + mi * 16 + la;
                    uint32_t ad = abase + m * 128 + ((ks * 32 + lb * 16) ^ lmask);
                    LDSM_X4(fa[mi][0], fa[mi][1], fa[mi][2], fa[mi][3], ad);
                }
#pragma unroll
                for (int nb = 0; nb < 4; ++nb) {
                    int kr = ks * 16 + la;
                    uint32_t bd = bbase + kr * 256 +
                                  (((wn * 64 + nb * 16 + lb * 8) * 2) ^ lmask);
                    LDSM_X4_T(fb[nb][0], fb[nb][1], fb[nb][2], fb[nb][3], bd);
                }
#pragma unroll
                for (int mi = 0; mi < 2; ++mi)
#pragma unroll
                    for (int ni = 0; ni < 8; ++ni)
                        mma16816(acc[mi][ni], fa[mi], &fb[ni >> 1][(ni & 1) * 2]);
            }

            if (kb == 7) {
                // fold 128-col n-chunk: bias + leaky + dot(W2)
                int ncb = nc * 128 + wn * 64 + (lane & 3) * 2;
#pragma unroll
                for (int ni = 0; ni < 8; ++ni) {
                    int n = ncb + ni * 8;
                    float2 p0 = bw[n];
                    float2 p1 = bw[n + 1];
#pragma unroll
                    for (int mi = 0; mi < 2; ++mi) {
                        rowacc[mi * 2 + 0] = fmaf(lrelu(acc[mi][ni][0] + p0.x), p0.y, rowacc[mi * 2 + 0]);
                        rowacc[mi * 2 + 0] = fmaf(lrelu(acc[mi][ni][1] + p1.x), p1.y, rowacc[mi * 2 + 0]);
                        rowacc[mi * 2 + 1] = fmaf(lrelu(acc[mi][ni][2] + p0.x), p0.y, rowacc[mi * 2 + 1]);
                        rowacc[mi * 2 + 1] = fmaf(lrelu(acc[mi][ni][3] + p1.x), p1.y, rowacc[mi * 2 + 1]);
                        acc[mi][ni][0] = 0.f; acc[mi][ni][1] = 0.f;
                        acc[mi][ni][2] = 0.f; acc[mi][ni][3] = 0.f;
                    }
                }
            }
        }

        // ---- per-tile epilogue ----
#pragma unroll
        for (int i = 0; i < 4; ++i) {
            rowacc[i] += __shfl_xor_sync(0xffffffffu, rowacc[i], 1);
            rowacc[i] += __shfl_xor_sync(0xffffffffu, rowacc[i], 2);
        }
        if ((lane & 3) == 0) {
            int rq = lane >> 2;
            int rbase = wm * 32;
            int col = half * 2 + wn;
            part[(rbase +  0 + rq) * 4 + col] = rowacc[0];
            part[(rbase +  8 + rq) * 4 + col] = rowacc[1];
            part[(rbase + 16 + rq) * 4 + col] = rowacc[2];
            part[(rbase + 24 + rq) * 4 + col] = rowacc[3];
        }
        __syncthreads();
        if (tid < 128) {
            float s = part[tid * 4] + part[tid * 4 + 1] + part[tid * 4 + 2] +
                      part[tid * 4 + 3] + b2g[h];
            s = lrelu(s);
            out[(size_t)(m0 + tid) * HH + h] = s;
        }
        rowacc[0] = rowacc[1] = rowacc[2] = rowacc[3] = 0.f;

        // reload bw for the next tile (own-half range; ordered vs first read
        // at next t>=7 by the full syncs at next t=0/t=2)
        if (tile + NSM < NTILES) {
            int hn = (tile + NSM) >> 4;
#pragma unroll
            for (int i = 0; i < 4; ++i) {
                int n = half * 1024 + i * 256 + ht;
                bw[n] = make_float2(b1g[hn * HID + n], w2g[hn * HID + n]);
            }
        }
        // part WAR (next tile's epilogue write vs this tile's read) is
        // ordered by the full __syncthreads at next tile's t=0.
    }
}

// ============================================================================
// Launch
// ============================================================================
extern "C" void kernel_launch(void* const* d_in, const int* in_sizes, int n_in,
                              void* d_out, int out_size) {
    const float* x  = (const float*)d_in[0];
    const float* W1 = (const float*)d_in[1];
    const float* b1 = (const float*)d_in[2];
    const float* W2 = (const float*)d_in[3];
    const float* b2 = (const float*)d_in[4];
    float* out = (float*)d_out;

    convert_all_kernel<<<33280, 256>>>(x, W1);

    cudaFuncSetAttribute(mhmlp_main, cudaFuncAttributeMaxDynamicSharedMemorySize, SMEM_TOTAL);
    mhmlp_main<<<NSM, NTHREADS, SMEM_TOTAL>>>(b1, W2, b2, out);
}

// round 14
// speedup vs baseline: 1.4172x; 1.0106x over previous
#include <cuda_runtime.h>
#include <cuda_fp16.h>
#include <cstdint>

// ============================================================================
// MHMLP: out[b,h] = lrelu( sum_n lrelu( x[b,:]·W1[h,:,n] + b1[h,n] ) * W2[h,n] + b2[h] )
// B=2048, H=64, D=512(K), HID=2048(N). fp32 in/out, fp16 HMMA (rt4 full-rate).
// R14: CTA-level independence via OCCUPANCY 2. CTA = 64m x 2048n, 256 thr,
// 8 warps (2m x 4n) of the proven 32m x 64n tiles. X streamed (2 x 8KB
// blocks), W double-buffered 64k x 256n chunks. smem 81KB, 128 regs ->
// 2 fully independent CTAs per SM cover each other's barrier convoys.
// Grid 2048 / 296 slots = 6.92 (same clean quantization as champion R5).
// ============================================================================
#define BB   2048
#define HH   64
#define DD   512
#define HID  2048

__device__ __half  g_W16[(size_t)HH * DD * HID];    // [h][d][n] fp16
__device__ __half  g_X16[(size_t)BB * DD];          // [b][d]   fp16
__device__ float4  g_BW4[(size_t)HH * HID / 2];     // {b1[n],w2[n],b1[n+1],w2[n+1]}

__device__ __forceinline__ uint32_t smem_to_u32(const void* p) {
    uint32_t a;
    asm("{ .reg .u64 t; cvta.to.shared.u64 t, %1; cvt.u32.u64 %0, t; }" : "=r"(a) : "l"(p));
    return a;
}
__device__ __forceinline__ void cp_async_16(uint32_t dst, const void* src) {
    asm volatile("cp.async.cg.shared.global [%0], [%1], 16;" :: "r"(dst), "l"(src));
}
#define CP_COMMIT()   asm volatile("cp.async.commit_group;" ::: "memory")
#define CP_WAIT0()    asm volatile("cp.async.wait_group 0;" ::: "memory")

#define LDSM_X4(r0, r1, r2, r3, addr) \
    asm volatile("ldmatrix.sync.aligned.m8n8.x4.shared.b16 {%0,%1,%2,%3}, [%4];" \
        : "=r"(r0), "=r"(r1), "=r"(r2), "=r"(r3) : "r"(addr))
#define LDSM_X4_T(r0, r1, r2, r3, addr) \
    asm volatile("ldmatrix.sync.aligned.m8n8.x4.trans.shared.b16 {%0,%1,%2,%3}, [%4];" \
        : "=r"(r0), "=r"(r1), "=r"(r2), "=r"(r3) : "r"(addr))

__device__ __forceinline__ void mma16816(float* c, const uint32_t* a, const uint32_t* b) {
    asm volatile(
        "mma.sync.aligned.m16n8k16.row.col.f32.f16.f16.f32 "
        "{%0,%1,%2,%3}, {%4,%5,%6,%7}, {%8,%9}, {%0,%1,%2,%3};"
        : "+f"(c[0]), "+f"(c[1]), "+f"(c[2]), "+f"(c[3])
        : "r"(a[0]), "r"(a[1]), "r"(a[2]), "r"(a[3]), "r"(b[0]), "r"(b[1]));
}

__device__ __forceinline__ float lrelu(float v) {
    return fmaxf(v, 0.f) + 0.01f * fminf(v, 0.f);
}

// ============================================================================
// Merged pre-pass:
//   blocks [0,512):       x fp32 -> fp16
//   blocks [512,33280):   W1 fp32 -> fp16
//   blocks [33280,33312): build g_BW4 (b1/W2 interleaved)
// ============================================================================
__global__ void convert_all_kernel(const float* __restrict__ x,
                                   const float* __restrict__ W1,
                                   const float* __restrict__ b1,
                                   const float* __restrict__ w2) {
    if (blockIdx.x >= 33280) {
        int g = (blockIdx.x - 33280) * 256 + threadIdx.x;
        float2* bw2 = reinterpret_cast<float2*>(g_BW4);
#pragma unroll
        for (int i = 0; i < 16; ++i) {
            int e = g + i * 8192;                           // HH*HID = 131072
            bw2[e] = make_float2(b1[e], w2[e]);
        }
        return;
    }
    const float* src;
    __half* dst;
    size_t g;
    if (blockIdx.x < 512) {
        g = (size_t)blockIdx.x * 256 + threadIdx.x;
        src = x;  dst = g_X16;
    } else {
        g = (size_t)(blockIdx.x - 512) * 256 + threadIdx.x;
        src = W1; dst = g_W16;
    }
    const float4* p = reinterpret_cast<const float4*>(src) + g * 2;
    float4 a = p[0], b = p[1];
    __half2 h0 = __floats2half2_rn(a.x, a.y), h1 = __floats2half2_rn(a.z, a.w);
    __half2 h2 = __floats2half2_rn(b.x, b.y), h3 = __floats2half2_rn(b.z, b.w);
    uint4 o;
    o.x = *reinterpret_cast<uint32_t*>(&h0);
    o.y = *reinterpret_cast<uint32_t*>(&h1);
    o.z = *reinterpret_cast<uint32_t*>(&h2);
    o.w = *reinterpret_cast<uint32_t*>(&h3);
    *reinterpret_cast<uint4*>(dst + g * 8) = o;
}

// ============================================================================
// Main fused kernel
// Grid: 2048 = 64 heads x 32 m-tiles (64 rows). 256 threads = 8 warps,
// warp grid 2m x 4n, warp tile 32m x 64n. 64 iterations: 8 n-chunks (256n)
// x 8 k-blocks (64k). X double-buffered 8KB blocks (streamed), W double-
// buffered 32KB chunks. One __syncthreads per iter; the OTHER resident CTA
// covers the convoy.
//
// SMEM (per CTA, 82944 B -> 2 CTAs/SM):
//   [0..16384)     X: 2 bufs x (64m x 64k), 128B rows, swizzled
//   [16384..81920) W: 2 bufs x (64k x 256n), 512B rows, swizzled
//   [81920..82944) part: float[64][4]
// ============================================================================
#define SM_X    0
#define SM_W    16384
#define SM_PART 81920
#define SMEM_TOTAL 82944
#define NTHREADS 256

// fill W chunk c (c in [0,64): nc=c>>3, kb=c&7) into buffer (c&1)
__device__ __forceinline__ void fill_w_chunk(const __half* __restrict__ Wh,
                                             uint32_t sb, int c, int tid) {
    int nc = c >> 3;
    int kb = c & 7;
    uint32_t base = sb + SM_W + (c & 1) * 32768;
    const __half* src = Wh + (size_t)(kb * 64) * HID + nc * 256;
#pragma unroll
    for (int i = 0; i < 8; ++i) {
        int idx = i * NTHREADS + tid;           // 2048 chunks of 16B
        int kr = idx >> 5, j = idx & 31;        // row kr (64), 16B unit j (32)
        uint32_t dst = base + kr * 512 + ((j * 16) ^ ((kr & 7) << 4));
        cp_async_16(dst, src + (size_t)kr * HID + j * 8);
    }
}

// fill X block kb (8KB, 64 rows x 64k) into buffer buf
__device__ __forceinline__ void fill_x_block(uint32_t sb, int m0, int kb,
                                             int buf, int tid) {
#pragma unroll
    for (int q = 0; q < 2; ++q) {
        int idx = q * NTHREADS + tid;           // 512 chunks of 16B
        int m = idx >> 3, jj = idx & 7;
        uint32_t dst = sb + SM_X + buf * 8192 + m * 128 + ((jj * 16) ^ ((m & 7) << 4));
        cp_async_16(dst, g_X16 + (size_t)(m0 + m) * DD + kb * 64 + jj * 8);
    }
}

__global__ void __launch_bounds__(NTHREADS, 2) mhmlp_main(
    const float* __restrict__ b2g, float* __restrict__ out)
{
    extern __shared__ char smem[];
    uint32_t sb = smem_to_u32(smem);
    int tid  = threadIdx.x;
    int lane = tid & 31;
    int wid  = tid >> 5;
    int wm   = wid >> 2;        // 0..1 (32-row band of 64m)
    int wn   = wid & 3;         // 0..3 (64-col quarter of the 256n chunk)
    int h  = blockIdx.x >> 5;
    int m0 = (blockIdx.x & 31) * 64;

    const __half* Wh = g_W16 + (size_t)h * DD * HID;

    // ---- initial fills: X block 0 (buf 0) + W chunk 0 (buf 0) ----
    fill_x_block(sb, m0, 0, 0, tid);
    fill_w_chunk(Wh, sb, 0, tid);
    CP_COMMIT();
    CP_WAIT0();
    __syncthreads();

    float acc[2][8][4];
#pragma unroll
    for (int mi = 0; mi < 2; ++mi)
#pragma unroll
        for (int ni = 0; ni < 8; ++ni)
#pragma unroll
            for (int r = 0; r < 4; ++r) acc[mi][ni][r] = 0.f;
    float rowacc[4] = {0.f, 0.f, 0.f, 0.f};

    int la = lane & 15;
    int lb = lane >> 4;
    int lmask = (lane & 7) << 4;
    const float4* bw4 = g_BW4 + (size_t)h * (HID / 2);

    uint32_t fa[2][4];
    uint32_t fb[4][4];

    for (int t = 0; t < 64; ++t) {
        if (t > 0) {
            CP_WAIT0();         // fills committed during t-1 landed
            __syncthreads();
        }
        if (t + 1 < 64) {       // prefetch X block + W chunk for t+1
            fill_x_block(sb, m0, (t + 1) & 7, (t + 1) & 1, tid);
            fill_w_chunk(Wh, sb, t + 1, tid);
            CP_COMMIT();
        }

        int nc = t >> 3;
        int kb = t & 7;
        (void)kb;
        uint32_t abase = sb + SM_X + (t & 1) * 8192;
        uint32_t bbase = sb + SM_W + (t & 1) * 32768;

#pragma unroll
        for (int ks = 0; ks < 4; ++ks) {
#pragma unroll
            for (int mi = 0; mi < 2; ++mi) {
                int m = wm * 32 + mi * 16 + la;
                uint32_t ad = abase + m * 128 + ((ks * 32 + lb * 16) ^ lmask);
                LDSM_X4(fa[mi][0], fa[mi][1], fa[mi][2], fa[mi][3], ad);
            }
#pragma unroll
            for (int nb = 0; nb < 4; ++nb) {
                int kr = ks * 16 + la;
                uint32_t bd = bbase + kr * 512 +
                              (((wn * 64 + nb * 16 + lb * 8) * 2) ^ lmask);
                LDSM_X4_T(fb[nb][0], fb[nb][1], fb[nb][2], fb[nb][3], bd);
            }
#pragma unroll
            for (int mi = 0; mi < 2; ++mi)
#pragma unroll
                for (int ni = 0; ni < 8; ++ni)
                    mma16816(acc[mi][ni], fa[mi], &fb[ni >> 1][(ni & 1) * 2]);
        }

        if ((t & 7) == 7) {
            // fold this 256-col n-chunk: bias + leaky + dot(W2)
            int fbase = nc * 128 + wn * 32 + (lane & 3);   // float4 index
#pragma unroll
            for (int ni = 0; ni < 8; ++ni) {
                float4 v = bw4[fbase + ni * 4];            // {b1,w2,b1',w2'}
#pragma unroll
                for (int mi = 0; mi < 2; ++mi) {
                    rowacc[mi * 2 + 0] = fmaf(lrelu(acc[mi][ni][0] + v.x), v.y, rowacc[mi * 2 + 0]);
                    rowacc[mi * 2 + 0] = fmaf(lrelu(acc[mi][ni][1] + v.z), v.w, rowacc[mi * 2 + 0]);
                    rowacc[mi * 2 + 1] = fmaf(lrelu(acc[mi][ni][2] + v.x), v.y, rowacc[mi * 2 + 1]);
                    rowacc[mi * 2 + 1] = fmaf(lrelu(acc[mi][ni][3] + v.z), v.w, rowacc[mi * 2 + 1]);
                    acc[mi][ni][0] = 0.f; acc[mi][ni][1] = 0.f;
                    acc[mi][ni][2] = 0.f; acc[mi][ni][3] = 0.f;
                }
            }
        }
    }

    // ---- reduce rowacc across the 4 lanes sharing each row ----
#pragma unroll
    for (int i = 0; i < 4; ++i) {
        rowacc[i] += __shfl_xor_sync(0xffffffffu, rowacc[i], 1);
        rowacc[i] += __shfl_xor_sync(0xffffffffu, rowacc[i], 2);
    }
    float* part = reinterpret_cast<float*>(smem + SM_PART);
    if ((lane & 3) == 0) {
        int rq = lane >> 2;                   // 0..7
        int rbase = wm * 32;
        part[(rbase +  0 + rq) * 4 + wn] = rowacc[0];
        part[(rbase +  8 + rq) * 4 + wn] = rowacc[1];
        part[(rbase + 16 + rq) * 4 + wn] = rowacc[2];
        part[(rbase + 24 + rq) * 4 + wn] = rowacc[3];
    }
    __syncthreads();
    if (tid < 64) {
        float s = part[tid * 4] + part[tid * 4 + 1] + part[tid * 4 + 2] +
                  part[tid * 4 + 3] + b2g[h];
        s = lrelu(s);
        out[(size_t)(m0 + tid) * HH + h] = s;
    }
}

// ============================================================================
// Launch
// ============================================================================
extern "C" void kernel_launch(void* const* d_in, const int* in_sizes, int n_in,
                              void* d_out, int out_size) {
    const float* x  = (const float*)d_in[0];
    const float* W1 = (const float*)d_in[1];
    const float* b1 = (const float*)d_in[2];
    const float* W2 = (const float*)d_in[3];
    const float* b2 = (const float*)d_in[4];
    float* out = (float*)d_out;

    convert_all_kernel<<<33312, 256>>>(x, W1, b1, W2);

    cudaFuncSetAttribute(mhmlp_main, cudaFuncAttributeMaxDynamicSharedMemorySize, SMEM_TOTAL);
    mhmlp_main<<<2048, NTHREADS, SMEM_TOTAL>>>(b2, out);
}

// round 15
// speedup vs baseline: 1.6344x; 1.1532x over previous
#include <cuda_runtime.h>
#include <cuda_fp16.h>
#include <cstdint>

// ============================================================================
// MHMLP: out[b,h] = lrelu( sum_n lrelu( x[b,:]·W1[h,:,n] + b1[h,n] ) * W2[h,n] + b2[h] )
// B=2048, H=64, D=512(K), HID=2048(N). fp32 in/out, fp16 HMMA compute.
// FINAL (champion, R5): one CTA = two independent pipeline halves (split by n,
// own W double buffers, own named barriers, own cp.async groups). 16 warps,
// warp tile 32m x 64n, 64 iterations of 128n x 64k. Session-measured optimum:
// R6(quarters) R7(triple-buf) R8(64x64 tiles) R9(split barriers) R10(fp16acc)
// R12(fused cvt) R13(persistent) R14(occ2) all regressed or neutral vs this.
// ============================================================================
#define BB   2048
#define HH   64
#define DD   512
#define HID  2048

__device__ __half  g_W16[(size_t)HH * DD * HID];    // [h][d][n] fp16
__device__ __half  g_X16[(size_t)BB * DD];          // [b][d]   fp16
__device__ float4  g_BW4[(size_t)HH * HID / 2];     // {b1[n],w2[n],b1[n+1],w2[n+1]}

__device__ __forceinline__ uint32_t smem_to_u32(const void* p) {
    uint32_t a;
    asm("{ .reg .u64 t; cvta.to.shared.u64 t, %1; cvt.u32.u64 %0, t; }" : "=r"(a) : "l"(p));
    return a;
}
__device__ __forceinline__ void cp_async_16(uint32_t dst, const void* src) {
    asm volatile("cp.async.cg.shared.global [%0], [%1], 16;" :: "r"(dst), "l"(src));
}
#define CP_COMMIT()   asm volatile("cp.async.commit_group;" ::: "memory")
#define CP_WAIT_ALL() asm volatile("cp.async.wait_group 0;" ::: "memory")

#define LDSM_X4(r0, r1, r2, r3, addr) \
    asm volatile("ldmatrix.sync.aligned.m8n8.x4.shared.b16 {%0,%1,%2,%3}, [%4];" \
        : "=r"(r0), "=r"(r1), "=r"(r2), "=r"(r3) : "r"(addr))
#define LDSM_X4_T(r0, r1, r2, r3, addr) \
    asm volatile("ldmatrix.sync.aligned.m8n8.x4.trans.shared.b16 {%0,%1,%2,%3}, [%4];" \
        : "=r"(r0), "=r"(r1), "=r"(r2), "=r"(r3) : "r"(addr))

__device__ __forceinline__ void mma16816(float* c, const uint32_t* a, const uint32_t* b) {
    asm volatile(
        "mma.sync.aligned.m16n8k16.row.col.f32.f16.f16.f32 "
        "{%0,%1,%2,%3}, {%4,%5,%6,%7}, {%8,%9}, {%0,%1,%2,%3};"
        : "+f"(c[0]), "+f"(c[1]), "+f"(c[2]), "+f"(c[3])
        : "r"(a[0]), "r"(a[1]), "r"(a[2]), "r"(a[3]), "r"(b[0]), "r"(b[1]));
}

__device__ __forceinline__ float lrelu(float v) {
    return fmaxf(v, 0.f) + 0.01f * fminf(v, 0.f);
}

// ============================================================================
// Merged pre-pass:
//   blocks [0,512):       x fp32 -> fp16
//   blocks [512,33280):   W1 fp32 -> fp16
//   blocks [33280,33312): build g_BW4 (b1/W2 interleaved)
// ============================================================================
__global__ void convert_all_kernel(const float* __restrict__ x,
                                   const float* __restrict__ W1,
                                   const float* __restrict__ b1,
                                   const float* __restrict__ w2) {
    if (blockIdx.x >= 33280) {
        int g = (blockIdx.x - 33280) * 256 + threadIdx.x;   // 8192 threads
        float2* bw2 = reinterpret_cast<float2*>(g_BW4);
#pragma unroll
        for (int i = 0; i < 16; ++i) {
            int e = g + i * 8192;                           // HH*HID = 131072
            bw2[e] = make_float2(b1[e], w2[e]);
        }
        return;
    }
    const float* src;
    __half* dst;
    size_t g;
    if (blockIdx.x < 512) {
        g = (size_t)blockIdx.x * 256 + threadIdx.x;
        src = x;  dst = g_X16;
    } else {
        g = (size_t)(blockIdx.x - 512) * 256 + threadIdx.x;
        src = W1; dst = g_W16;
    }
    const float4* p = reinterpret_cast<const float4*>(src) + g * 2;
    float4 a = p[0], b = p[1];
    __half2 h0 = __floats2half2_rn(a.x, a.y), h1 = __floats2half2_rn(a.z, a.w);
    __half2 h2 = __floats2half2_rn(b.x, b.y), h3 = __floats2half2_rn(b.z, b.w);
    uint4 o;
    o.x = *reinterpret_cast<uint32_t*>(&h0);
    o.y = *reinterpret_cast<uint32_t*>(&h1);
    o.z = *reinterpret_cast<uint32_t*>(&h2);
    o.w = *reinterpret_cast<uint32_t*>(&h3);
    *reinterpret_cast<uint4*>(dst + g * 8) = o;
}

// ============================================================================
// Main fused kernel
// Grid: 1024 = 64 heads x 16 m-tiles. 512 threads = 16 warps.
// Warps 0-7 = half 0 (n-chunks 0-7), warps 8-15 = half 1 (n-chunks 8-15).
// Each half: 4m x 2n warps, warp tile 32m x 64n, own W double buffer (16KB
// chunks), own named barrier, own cp.async groups. X tile shared (read-only).
//
// SMEM:
//   [0..131072)        X: [kb][128m][64k halves], 128B rows, swizzled
//   [131072..196608)   W: 2 halves x 2 bufs x (64k x 128n), 256B rows, swizzled
//   [196608..198656)   part: float[128][4]
// ============================================================================
#define SM_X    0
#define SM_W    131072
#define SM_PART 196608
#define SMEM_TOTAL 198656
#define NTHREADS 512

__device__ __forceinline__ void fill_w_chunk(const __half* __restrict__ Wh,
                                             uint32_t sb, int half, int t, int ht) {
    int nc = half * 8 + (t >> 3);
    int kb = t & 7;
    uint32_t base = sb + SM_W + half * 32768 + (t & 1) * 16384;
    const __half* src = Wh + (size_t)(kb * 64) * HID + nc * 128;
#pragma unroll
    for (int i = 0; i < 4; ++i) {
        int idx = i * 256 + ht;                 // 1024 chunks of 16B
        int kr = idx >> 4, j = idx & 15;
        uint32_t dst = base + kr * 256 + ((j * 16) ^ ((kr & 7) << 4));
        cp_async_16(dst, src + (size_t)kr * HID + j * 8);
    }
}

__global__ void __launch_bounds__(NTHREADS, 1) mhmlp_main(
    const float* __restrict__ b2g, float* __restrict__ out)
{
    extern __shared__ char smem[];
    uint32_t sb = smem_to_u32(smem);
    int tid  = threadIdx.x;
    int lane = tid & 31;
    int wid  = tid >> 5;
    int half = wid >> 3;        // 0 or 1
    int hw   = wid & 7;         // warp index within half
    int wm   = hw >> 1;         // 0..3 (32-row band)
    int wn   = hw & 1;          // 0..1 (64-col half of the 128n chunk)
    int ht   = tid & 255;       // thread index within half
    int h  = blockIdx.x >> 4;
    int m0 = (blockIdx.x & 15) * 128;

    const __half* Wh = g_W16 + (size_t)h * DD * HID;

    // ---- X tile fill (all 512 threads): [kb][m][64k], swizzled 128B rows ----
#pragma unroll
    for (int i = 0; i < 16; ++i) {
        int idx = i * NTHREADS + tid;            // 8192 chunks of 16B
        int m = idx >> 6, j = idx & 63;
        int kb = j >> 3, jj = j & 7;
        uint32_t dst = sb + SM_X + kb * 16384 + m * 128 + ((jj * 16) ^ ((m & 7) << 4));
        cp_async_16(dst, g_X16 + (size_t)(m0 + m) * DD + kb * 64 + jj * 8);
    }
    // ---- each half fills its W chunk 0 ----
    fill_w_chunk(Wh, sb, half, 0, ht);
    CP_COMMIT();
    CP_WAIT_ALL();
    __syncthreads();            // X + both W0 chunks visible to all

    float acc[2][8][4];
#pragma unroll
    for (int mi = 0; mi < 2; ++mi)
#pragma unroll
        for (int ni = 0; ni < 8; ++ni)
#pragma unroll
            for (int r = 0; r < 4; ++r) acc[mi][ni][r] = 0.f;
    float rowacc[4] = {0.f, 0.f, 0.f, 0.f};

    int la = lane & 15;
    int lb = lane >> 4;
    int lmask = (lane & 7) << 4;
    int barid = 1 + half;
    const float4* bw4 = g_BW4 + (size_t)h * (HID / 2);

    uint32_t fa[2][4];
    uint32_t fb[4][4];

    for (int t = 0; t < 64; ++t) {
        // W(t) ready: it was committed at top of t-1 (or init for t=0)
        CP_WAIT_ALL();
        asm volatile("bar.sync %0, %1;" :: "r"(barid), "r"(256) : "memory");
        // prefetch W(t+1) into the buffer whose reads finished at t-1
        if (t + 1 < 64) fill_w_chunk(Wh, sb, half, t + 1, ht);
        CP_COMMIT();

        int nc = half * 8 + (t >> 3);
        int kb = t & 7;
        uint32_t abase = sb + SM_X + kb * 16384;
        uint32_t bbase = sb + SM_W + half * 32768 + (t & 1) * 16384;

#pragma unroll
        for (int ks = 0; ks < 4; ++ks) {
#pragma unroll
            for (int mi = 0; mi < 2; ++mi) {
                int m = wm * 32 + mi * 16 + la;
                uint32_t ad = abase + m * 128 + ((ks * 32 + lb * 16) ^ lmask);
                LDSM_X4(fa[mi][0], fa[mi][1], fa[mi][2], fa[mi][3], ad);
            }
#pragma unroll
            for (int nb = 0; nb < 4; ++nb) {
                int kr = ks * 16 + la;
                uint32_t bd = bbase + kr * 256 +
                              (((wn * 64 + nb * 16 + lb * 8) * 2) ^ lmask);
                LDSM_X4_T(fb[nb][0], fb[nb][1], fb[nb][2], fb[nb][3], bd);
            }
#pragma unroll
            for (int mi = 0; mi < 2; ++mi)
#pragma unroll
                for (int ni = 0; ni < 8; ++ni)
                    mma16816(acc[mi][ni], fa[mi], &fb[ni >> 1][(ni & 1) * 2]);
        }

        if (kb == 7) {
            // fold 128-col n-chunk: bias + leaky + dot(W2); bw from L2-hot global
            int fbase = nc * 64 + wn * 32 + (lane & 3);   // float4 index
#pragma unroll
            for (int ni = 0; ni < 8; ++ni) {
                float4 v = bw4[fbase + ni * 4];           // {b1,w2,b1',w2'}
#pragma unroll
                for (int mi = 0; mi < 2; ++mi) {
                    rowacc[mi * 2 + 0] = fmaf(lrelu(acc[mi][ni][0] + v.x), v.y, rowacc[mi * 2 + 0]);
                    rowacc[mi * 2 + 0] = fmaf(lrelu(acc[mi][ni][1] + v.z), v.w, rowacc[mi * 2 + 0]);
                    rowacc[mi * 2 + 1] = fmaf(lrelu(acc[mi][ni][2] + v.x), v.y, rowacc[mi * 2 + 1]);
                    rowacc[mi * 2 + 1] = fmaf(lrelu(acc[mi][ni][3] + v.z), v.w, rowacc[mi * 2 + 1]);
                    acc[mi][ni][0] = 0.f; acc[mi][ni][1] = 0.f;
                    acc[mi][ni][2] = 0.f; acc[mi][ni][3] = 0.f;
                }
            }
        }
    }

    // ---- reduce rowacc across the 4 lanes sharing each row ----
#pragma unroll
    for (int i = 0; i < 4; ++i) {
        rowacc[i] += __shfl_xor_sync(0xffffffffu, rowacc[i], 1);
        rowacc[i] += __shfl_xor_sync(0xffffffffu, rowacc[i], 2);
    }
    float* part = reinterpret_cast<float*>(smem + SM_PART);
    if ((lane & 3) == 0) {
        int rq = lane >> 2;                   // 0..7
        int rbase = wm * 32;
        int col = half * 2 + wn;
        part[(rbase +  0 + rq) * 4 + col] = rowacc[0];
        part[(rbase +  8 + rq) * 4 + col] = rowacc[1];
        part[(rbase + 16 + rq) * 4 + col] = rowacc[2];
        part[(rbase + 24 + rq) * 4 + col] = rowacc[3];
    }
    __syncthreads();
    if (tid < 128) {
        float s = part[tid * 4] + part[tid * 4 + 1] + part[tid * 4 + 2] +
                  part[tid * 4 + 3] + b2g[h];
        s = lrelu(s);
        out[(size_t)(m0 + tid) * HH + h] = s;
    }
}

// ============================================================================
// Launch
// ============================================================================
extern "C" void kernel_launch(void* const* d_in, const int* in_sizes, int n_in,
                              void* d_out, int out_size) {
    const float* x  = (const float*)d_in[0];
    const float* W1 = (const float*)d_in[1];
    const float* b1 = (const float*)d_in[2];
    const float* W2 = (const float*)d_in[3];
    const float* b2 = (const float*)d_in[4];
    float* out = (float*)d_out;

    convert_all_kernel<<<33312, 256>>>(x, W1, b1, W2);

    cudaFuncSetAttribute(mhmlp_main, cudaFuncAttributeMaxDynamicSharedMemorySize, SMEM_TOTAL);
    mhmlp_main<<<1024, NTHREADS, SMEM_TOTAL>>>(b2, out);
}